// round 16
// baseline (speedup 1.0000x reference)
#include <cuda_runtime.h>
#include <cuda_fp16.h>
#include <math.h>
#include <stdint.h>

#define N_TOK 32768
#define DIM   512
#define NE    8
#define NF    2048
#define NCAP  4096

// GEMM tiling
#define BM 128
#define BN 256
#define BKC 64
#define GTHREADS 512
// per-stage SMEM: A(16K) B(32K) = 48K, 4 stages
#define PART_BYTES 16384
#define STAGE_BYTES 49152
#define NSTAGE 4
#define DYN_SMEM (NSTAGE * STAGE_BYTES)
#define OUTSCALE 256.0f
#define INV_OUTSCALE (1.0f / 256.0f)

// ---------------- scratch (device globals; no allocs allowed) ----------------
__device__ float    g_logits[NE * N_TOK];        // [E][N]
__device__ float    g_sumexp[NE];
__device__ float    g_partsum[NE][32];
__device__ int      g_hist[NE][256];
__device__ unsigned g_thr[NE];
__device__ int      g_gcnt[NE];
__device__ int      g_needeq[NE];
__device__ int      g_cnt[NE];
__device__ int      g_eqcnt[NE];
__device__ int      g_arrive[NE];
__device__ int      g_flag[NE];
__device__ int      g_eqbuf[NE * N_TOK];
__device__ int      g_idx[NE * NCAP];
__device__ float    g_vals[NE * NCAP];
__device__ int      g_slot[NE * N_TOK];
__device__ __align__(16) __half g_xh[N_TOK * DIM];
__device__ __align__(16) __half g_w1t[NE * NF * DIM];   // [E][F][D] fp16
__device__ __align__(16) __half g_w2t[NE * DIM * NF];   // [E][D][F] fp16
__device__ __align__(16) __half g_hh[NE * NCAP * NF];
__device__ __align__(16) __half g_oute[(size_t)NE * NCAP * DIM]; // x256 scaled

// ---------------- helpers ----------------
__device__ __forceinline__ uint32_t smem_u32(const void* p) {
    uint32_t a;
    asm("{ .reg .u64 t; cvta.to.shared.u64 t, %1; cvt.u32.u64 %0, t; }" : "=r"(a) : "l"(p));
    return a;
}
#define SWZ(o) ((o) ^ (((o) >> 3) & 0x70))

#define CP_ASYNC16(saddr, gptr) \
    asm volatile("cp.async.cg.shared.global [%0], [%1], 16;" :: "r"(saddr), "l"(gptr))
#define CP_COMMIT() asm volatile("cp.async.commit_group;")
#define CP_WAIT2()  asm volatile("cp.async.wait_group 2;")

#define LDSM4(r, addr) \
    asm volatile("ldmatrix.sync.aligned.x4.m8n8.shared.b16 {%0,%1,%2,%3}, [%4];" \
        : "=r"((r)[0]), "=r"((r)[1]), "=r"((r)[2]), "=r"((r)[3]) : "r"(addr))

#define MMA_F16(d, a, b0, b1) \
    asm volatile("mma.sync.aligned.m16n8k16.row.col.f32.f16.f16.f32 " \
        "{%0,%1,%2,%3},{%4,%5,%6,%7},{%8,%9},{%0,%1,%2,%3};" \
        : "+f"((d)[0]), "+f"((d)[1]), "+f"((d)[2]), "+f"((d)[3]) \
        : "r"((a)[0]), "r"((a)[1]), "r"((a)[2]), "r"((a)[3]), "r"(b0), "r"(b1))

__device__ __forceinline__ unsigned fkey(float f) {
    unsigned u = __float_as_uint(f);
    return (u & 0x80000000u) ? ~u : (u | 0x80000000u);
}

// ---------------- K1: fused x->fp16 + router logits ([E][N] layout) ----------------
__global__ __launch_bounds__(256) void k_prep_x(const float* __restrict__ x,
                                                const float* __restrict__ Wr) {
    __shared__ float sW[NE][DIM];
    int tid = threadIdx.x;
    for (int i = tid; i < DIM * NE; i += 256) {
        int d = i >> 3, e = i & 7; // Wr[d][e]
        sW[e][d] = Wr[i];
    }
    __syncthreads();
    int warp = tid >> 5, lane = tid & 31;
    int n = blockIdx.x * 16 + warp * 2;
    const float* xr0 = x + (size_t)n * DIM;
    const float* xr1 = xr0 + DIM;
    float acc0[NE], acc1[NE];
#pragma unroll
    for (int e = 0; e < NE; e++) { acc0[e] = 0.f; acc1[e] = 0.f; }
#pragma unroll
    for (int it = 0; it < 4; it++) {
        int d0 = it * 128 + lane * 4;
        float4 v0 = *(const float4*)(xr0 + d0);
        float4 v1 = *(const float4*)(xr1 + d0);
        __half2 a01 = __halves2half2(__float2half_rn(v0.x), __float2half_rn(v0.y));
        __half2 a23 = __halves2half2(__float2half_rn(v0.z), __float2half_rn(v0.w));
        __half2 b01 = __halves2half2(__float2half_rn(v1.x), __float2half_rn(v1.y));
        __half2 b23 = __halves2half2(__float2half_rn(v1.z), __float2half_rn(v1.w));
        *(__half2*)(g_xh + (size_t)n * DIM + d0) = a01;
        *(__half2*)(g_xh + (size_t)n * DIM + d0 + 2) = a23;
        *(__half2*)(g_xh + (size_t)(n + 1) * DIM + d0) = b01;
        *(__half2*)(g_xh + (size_t)(n + 1) * DIM + d0 + 2) = b23;
#pragma unroll
        for (int e = 0; e < NE; e++) {
            float4 w = *(const float4*)&sW[e][d0];
            acc0[e] += v0.x * w.x + v0.y * w.y + v0.z * w.z + v0.w * w.w;
            acc1[e] += v1.x * w.x + v1.y * w.y + v1.z * w.z + v1.w * w.w;
        }
    }
#pragma unroll
    for (int e = 0; e < NE; e++) {
#pragma unroll
        for (int off = 16; off > 0; off >>= 1) {
            acc0[e] += __shfl_xor_sync(0xffffffffu, acc0[e], off);
            acc1[e] += __shfl_xor_sync(0xffffffffu, acc1[e], off);
        }
        if (lane == e) {
            g_logits[(size_t)e * N_TOK + n] = acc0[e];
            g_logits[(size_t)e * N_TOK + n + 1] = acc1[e];
        }
    }
}

// ---------------- prep: transpose [R,C] -> [C,R] fp16 ----------------
__global__ void k_tsplit(const float* __restrict__ in, __half* __restrict__ oh,
                         int R, int C) {
    __shared__ float t[32][33];
    int e = blockIdx.z;
    const float* ip = in + (size_t)e * R * C;
    int c0 = blockIdx.x * 32, r0 = blockIdx.y * 32;
    for (int i = threadIdx.y; i < 32; i += 8)
        t[i][threadIdx.x] = ip[(size_t)(r0 + i) * C + c0 + threadIdx.x];
    __syncthreads();
    size_t ob = (size_t)e * R * C;
    for (int i = threadIdx.y; i < 32; i += 8) {
        float v = t[threadIdx.x][i];
        oh[ob + (size_t)(c0 + i) * R + r0 + threadIdx.x] = __float2half_rn(v);
    }
}

// ---------------- K2: fused radix select (4 passes + compaction, one launch) ----------------
// grid (NE, 32), block 256. All 256 blocks co-resident -> per-expert software
// barriers (arrive counters + pass flags) are deadlock-free. Keys cached in regs.
__global__ __launch_bounds__(256) void k_select_fused() {
    int e = blockIdx.x, s = blockIdx.y, tid = threadIdx.x;
    __shared__ int hist[256];
    __shared__ float red[8];
    const float* lp = g_logits + (size_t)e * N_TOK + s * 1024;
    float l0 = lp[tid], l1 = lp[256 + tid], l2 = lp[512 + tid], l3 = lp[768 + tid];
    unsigned k0 = fkey(l0), k1 = fkey(l1), k2 = fkey(l2), k3 = fkey(l3);

    // partial sum(exp) for this slab
    {
        float se = expf(l0) + expf(l1) + expf(l2) + expf(l3);
        int lane = tid & 31, w = tid >> 5;
#pragma unroll
        for (int off = 16; off > 0; off >>= 1) se += __shfl_xor_sync(0xffffffffu, se, off);
        if (lane == 0) red[w] = se;
        __syncthreads();
        if (tid == 0) {
            float v = 0.f;
#pragma unroll
            for (int i = 0; i < 8; i++) v += red[i];
            g_partsum[e][s] = v;
        }
    }

    unsigned pref = 0u;
    for (int pass = 0; pass < 4; pass++) {
        int shift = 24 - 8 * pass;
        unsigned pmask = pass ? (0xFFFFFFFFu << (shift + 8)) : 0u;
        __syncthreads();
        hist[tid] = 0;
        __syncthreads();
        if ((k0 & pmask) == pref) atomicAdd(&hist[(k0 >> shift) & 255], 1);
        if ((k1 & pmask) == pref) atomicAdd(&hist[(k1 >> shift) & 255], 1);
        if ((k2 & pmask) == pref) atomicAdd(&hist[(k2 >> shift) & 255], 1);
        if ((k3 & pmask) == pref) atomicAdd(&hist[(k3 >> shift) & 255], 1);
        __syncthreads();
        if (hist[tid]) atomicAdd(&g_hist[e][tid], hist[tid]);
        __threadfence();
        __syncthreads();
        if (tid == 0) atomicAdd(&g_arrive[e], 1);

        if (s == 0) {
            if (tid == 0) {
                while (atomicAdd(&g_arrive[e], 0) < 32 * (pass + 1)) __nanosleep(64);
            }
            __syncthreads();
            __threadfence();
            int hv = g_hist[e][tid];
            g_hist[e][tid] = 0;          // ready for next pass / next launch
            hist[tid] = hv;
            __syncthreads();
            if (tid == 0) {
                int rem = pass ? g_needeq[e] : NCAP;
                int gc  = pass ? g_gcnt[e] : 0;
                int above = 0, b = 255;
                for (; b >= 0; b--) {
                    int hh = hist[b];
                    if (above + hh >= rem) break;
                    above += hh;
                }
                g_gcnt[e] = gc + above;
                g_needeq[e] = rem - above;
                g_thr[e] = pref | ((unsigned)b << shift);
                if (pass == 0) {
                    float v = 0.f;
#pragma unroll
                    for (int i = 0; i < 32; i++) v += g_partsum[e][i];
                    g_sumexp[e] = v;
                }
                if (pass == 3) { g_cnt[e] = 0; g_eqcnt[e] = 0; }
                __threadfence();
                atomicExch(&g_flag[e], pass + 1);
            }
        }
        if (tid == 0) {
            while (atomicAdd(&g_flag[e], 0) < pass + 1) __nanosleep(64);
        }
        __syncthreads();
        __threadfence();
        pref = g_thr[e];
    }

    // compaction (slot order free for > threshold; eq tokens deferred to k_eqfix)
    unsigned T = pref;
    float inv = 1.0f / g_sumexp[e];
    float ll[4] = {l0, l1, l2, l3};
    unsigned kk[4] = {k0, k1, k2, k3};
#pragma unroll
    for (int it = 0; it < 4; it++) {
        int n = s * 1024 + it * 256 + tid;
        unsigned k = kk[it];
        if (k > T) {
            int slot = atomicAdd(&g_cnt[e], 1);
            g_idx[e * NCAP + slot] = n;
            g_vals[e * NCAP + slot] = expf(ll[it]) * inv;
            g_slot[(size_t)e * N_TOK + n] = slot;
        } else if (k == T) {
            int p = atomicAdd(&g_eqcnt[e], 1);
            g_eqbuf[(size_t)e * N_TOK + p] = n;
        } else {
            g_slot[(size_t)e * N_TOK + n] = -1;
        }
    }
}

// ---------------- K3: deterministic tie-break for threshold-equal tokens ----------------
__global__ __launch_bounds__(256) void k_eqfix() {
    int e = blockIdx.x, tid = threadIdx.x;
    int neq = g_eqcnt[e], need = g_needeq[e], base = g_gcnt[e];
    float inv = 1.0f / g_sumexp[e];
    const int* buf = g_eqbuf + (size_t)e * N_TOK;
    for (int i = tid; i < neq; i += 256) {
        int t = buf[i];
        int rank = 0;
        for (int j = 0; j < neq; j++) rank += (buf[j] < t) ? 1 : 0;
        int slot = -1;
        if (rank < need) {
            slot = base + rank;
            g_idx[e * NCAP + slot] = t;
            g_vals[e * NCAP + slot] = expf(g_logits[(size_t)e * N_TOK + t]) * inv;
        }
        g_slot[(size_t)e * N_TOK + t] = slot;
    }
    if (tid == 0) { g_arrive[e] = 0; g_flag[e] = 0; }  // reset for next graph replay
}

// ======================================================================
// GEMM core (mma.sync fp16) — CTA 128x256, warp tile 32x64, 4-stage cp.async
// ======================================================================

__device__ __forceinline__ void mma_chunk(uint32_t sbase, int lane, int m0, int n0,
                                          float acc[2][8][4]) {
    const int lrow = lane & 15;
    const int ksel = (lane >> 4) * 16;
#pragma unroll
    for (int ks = 0; ks < 4; ks++) {
        uint32_t ahf[2][4], bhf[4][4];
        const int kb = ks * 32 + ksel;
#pragma unroll
        for (int am = 0; am < 2; am++) {
            uint32_t off = SWZ((uint32_t)((m0 + am * 16 + lrow) * 128 + kb));
            LDSM4(ahf[am], sbase + off);
        }
#pragma unroll
        for (int bg = 0; bg < 4; bg++) {
            uint32_t off = SWZ((uint32_t)((n0 + bg * 16 + lrow) * 128 + kb));
            LDSM4(bhf[bg], sbase + PART_BYTES + off);
        }
#pragma unroll
        for (int am = 0; am < 2; am++)
#pragma unroll
            for (int na = 0; na < 8; na++) {
                int bg = na >> 1, j = na & 1;
                MMA_F16(acc[am][na], ahf[am], bhf[bg][j], bhf[bg][j + 2]);
            }
    }
}

// ---------------- K4: GEMM1 (gathered A) + gelu -> g_hh ----------------
__global__ __launch_bounds__(GTHREADS) void k_gemm1_mma(const float* __restrict__ b1) {
    extern __shared__ __align__(16) char dsm[];
    __shared__ int s_ridx[BM];
    const int tid = threadIdx.x;
    const int e = blockIdx.z;
    const int mBase = blockIdx.y * BM;
    const int fBase = blockIdx.x * BN;
    if (tid < BM) s_ridx[tid] = g_idx[e * NCAP + mBase + tid];
    __syncthreads();

    const uint32_t sb = smem_u32(dsm);
    const __half* Wb = g_w1t + ((size_t)e * NF + fBase) * DIM;

    const int lane = tid & 31, wid = tid >> 5;
    const int m0 = (wid & 3) * 32, n0 = (wid >> 2) * 64;
    float acc[2][8][4];
#pragma unroll
    for (int a = 0; a < 2; a++)
#pragma unroll
        for (int b = 0; b < 8; b++)
#pragma unroll
            for (int cc = 0; cc < 4; cc++) acc[a][b][cc] = 0.f;

    const int NC = DIM / BKC; // 8
#define G1_LOAD(c, buf) do { \
    uint32_t stb = sb + (buf) * STAGE_BYTES; \
    _Pragma("unroll") \
    for (int it = 0; it < 2; it++) { \
        int idx = it * 512 + tid; \
        int row = idx >> 3, seg = idx & 7; \
        uint32_t so = stb + SWZ((uint32_t)(row * 128 + seg * 16)); \
        CP_ASYNC16(so, g_xh + (size_t)s_ridx[row] * DIM + (c) * BKC + seg * 8); \
    } \
    _Pragma("unroll") \
    for (int it = 0; it < 4; it++) { \
        int idx = it * 512 + tid; \
        int row = idx >> 3, seg = idx & 7; \
        uint32_t so = stb + PART_BYTES + SWZ((uint32_t)(row * 128 + seg * 16)); \
        CP_ASYNC16(so, Wb + (size_t)row * DIM + (c) * BKC + seg * 8); \
    } \
} while (0)

    G1_LOAD(0, 0); CP_COMMIT();
    G1_LOAD(1, 1); CP_COMMIT();
    G1_LOAD(2, 2); CP_COMMIT();
    int s_mma = 0, s_ld = 3;
    for (int c = 0; c < NC; c++) {
        CP_WAIT2();
        __syncthreads();
        if (c + 3 < NC) G1_LOAD(c + 3, s_ld);
        CP_COMMIT();
        mma_chunk(sb + s_mma * STAGE_BYTES, lane, m0, n0, acc);
        s_mma = (s_mma == NSTAGE - 1) ? 0 : s_mma + 1;
        s_ld = (s_ld == NSTAGE - 1) ? 0 : s_ld + 1;
    }
#undef G1_LOAD

    // epilogue: bias + gelu -> fp16
    const int r0 = lane >> 2, c0 = 2 * (lane & 3);
#pragma unroll
    for (int am = 0; am < 2; am++) {
        int gr0 = mBase + m0 + am * 16 + r0;
#pragma unroll
        for (int na = 0; na < 8; na++) {
            int gc = fBase + n0 + na * 8 + c0;
            float bb0 = b1[e * NF + gc], bb1 = b1[e * NF + gc + 1];
#pragma unroll
            for (int half = 0; half < 2; half++) {
                int gr = gr0 + half * 8;
                float v0 = acc[am][na][half * 2 + 0] + bb0;
                float v1 = acc[am][na][half * 2 + 1] + bb1;
                float gg0 = 0.5f * v0 * (1.0f + erff(v0 * 0.70710678118654752f));
                float gg1 = 0.5f * v1 * (1.0f + erff(v1 * 0.70710678118654752f));
                size_t o = ((size_t)(e * NCAP) + gr) * NF + gc;
                *(__half2*)(g_hh + o) =
                    __halves2half2(__float2half_rn(gg0), __float2half_rn(gg1));
            }
        }
    }
}

// ---------------- K5: GEMM2 + bias + gate -> g_oute (fp16, x256) ----------------
__global__ __launch_bounds__(GTHREADS) void k_gemm2_mma(const float* __restrict__ b2) {
    extern __shared__ __align__(16) char dsm2[];
    const int tid = threadIdx.x;
    const int e = blockIdx.z;
    const int mBase = blockIdx.y * BM;
    const int dBase = blockIdx.x * BN;

    const uint32_t sb = smem_u32(dsm2);
    const __half* Ahp = g_hh + ((size_t)(e * NCAP) + mBase) * NF;
    const __half* Wb = g_w2t + ((size_t)e * DIM + dBase) * NF;

    const int lane = tid & 31, wid = tid >> 5;
    const int m0 = (wid & 3) * 32, n0 = (wid >> 2) * 64;
    float acc[2][8][4];
#pragma unroll
    for (int a = 0; a < 2; a++)
#pragma unroll
        for (int b = 0; b < 8; b++)
#pragma unroll
            for (int cc = 0; cc < 4; cc++) acc[a][b][cc] = 0.f;

    const int NC = NF / BKC; // 32
#define G2_LOAD(c, buf) do { \
    uint32_t stb = sb + (buf) * STAGE_BYTES; \
    _Pragma("unroll") \
    for (int it = 0; it < 2; it++) { \
        int idx = it * 512 + tid; \
        int row = idx >> 3, seg = idx & 7; \
        uint32_t so = stb + SWZ((uint32_t)(row * 128 + seg * 16)); \
        CP_ASYNC16(so, Ahp + (size_t)row * NF + (c) * BKC + seg * 8); \
    } \
    _Pragma("unroll") \
    for (int it = 0; it < 4; it++) { \
        int idx = it * 512 + tid; \
        int row = idx >> 3, seg = idx & 7; \
        uint32_t so = stb + PART_BYTES + SWZ((uint32_t)(row * 128 + seg * 16)); \
        CP_ASYNC16(so, Wb + (size_t)row * NF + (c) * BKC + seg * 8); \
    } \
} while (0)

    G2_LOAD(0, 0); CP_COMMIT();
    G2_LOAD(1, 1); CP_COMMIT();
    G2_LOAD(2, 2); CP_COMMIT();
    int s_mma = 0, s_ld = 3;
    for (int c = 0; c < NC; c++) {
        CP_WAIT2();
        __syncthreads();
        if (c + 3 < NC) G2_LOAD(c + 3, s_ld);
        CP_COMMIT();
        mma_chunk(sb + s_mma * STAGE_BYTES, lane, m0, n0, acc);
        s_mma = (s_mma == NSTAGE - 1) ? 0 : s_mma + 1;
        s_ld = (s_ld == NSTAGE - 1) ? 0 : s_ld + 1;
    }
#undef G2_LOAD

    const int r0 = lane >> 2, c0 = 2 * (lane & 3);
#pragma unroll
    for (int am = 0; am < 2; am++) {
        int gr0 = mBase + m0 + am * 16 + r0;
        float sv0 = g_vals[e * NCAP + gr0] * OUTSCALE;
        float sv1 = g_vals[e * NCAP + gr0 + 8] * OUTSCALE;
#pragma unroll
        for (int na = 0; na < 8; na++) {
            int gc = dBase + n0 + na * 8 + c0;
            float bb0 = b2[e * DIM + gc], bb1 = b2[e * DIM + gc + 1];
            size_t o0 = ((size_t)(e * NCAP) + gr0) * DIM + gc;
            size_t o1 = o0 + (size_t)8 * DIM;
            *(__half2*)(g_oute + o0) =
                __halves2half2(__float2half_rn((acc[am][na][0] + bb0) * sv0),
                               __float2half_rn((acc[am][na][1] + bb1) * sv0));
            *(__half2*)(g_oute + o1) =
                __halves2half2(__float2half_rn((acc[am][na][2] + bb0) * sv1),
                               __float2half_rn((acc[am][na][3] + bb1) * sv1));
        }
    }
}

// ---------------- K6: deterministic gather-sum into output (4 tokens/block) ----------------
__global__ __launch_bounds__(512) void k_combine(float* __restrict__ out) {
    int sub = threadIdx.x >> 7;     // 0..3
    int t = threadIdx.x & 127;
    int n = blockIdx.x * 4 + sub;
    __shared__ int slots[4][NE];
    if (t < NE) slots[sub][t] = g_slot[(size_t)t * N_TOK + n];
    __syncthreads();
    float4 acc = make_float4(0.f, 0.f, 0.f, 0.f);
#pragma unroll
    for (int e = 0; e < NE; e++) {
        int s = slots[sub][e];
        if (s >= 0) {
            const __half* p = g_oute + ((size_t)(e * NCAP + s)) * DIM + t * 4;
            uint2 v = *(const uint2*)p;
            float2 fa = __half22float2(*(__half2*)&v.x);
            float2 fb = __half22float2(*(__half2*)&v.y);
            acc.x += fa.x; acc.y += fa.y; acc.z += fb.x; acc.w += fb.y;
        }
    }
    acc.x *= INV_OUTSCALE; acc.y *= INV_OUTSCALE;
    acc.z *= INV_OUTSCALE; acc.w *= INV_OUTSCALE;
    ((float4*)out)[(size_t)n * (DIM / 4) + t] = acc;
}

// ---------------- launch ----------------
extern "C" void kernel_launch(void* const* d_in, const int* in_sizes, int n_in,
                              void* d_out, int out_size) {
    const float* x  = (const float*)d_in[0];
    const float* Wr = (const float*)d_in[1];
    const float* W1 = (const float*)d_in[2];
    const float* b1 = (const float*)d_in[3];
    const float* W2 = (const float*)d_in[4];
    const float* b2 = (const float*)d_in[5];
    float* out = (float*)d_out;

    cudaFuncSetAttribute(k_gemm1_mma, cudaFuncAttributeMaxDynamicSharedMemorySize, DYN_SMEM);
    cudaFuncSetAttribute(k_gemm2_mma, cudaFuncAttributeMaxDynamicSharedMemorySize, DYN_SMEM);

    k_prep_x<<<N_TOK / 16, 256>>>(x, Wr);
    {
        __half *w1t, *w2t;
        cudaGetSymbolAddress((void**)&w1t, g_w1t);
        cudaGetSymbolAddress((void**)&w2t, g_w2t);
        k_tsplit<<<dim3(NF / 32, DIM / 32, NE), dim3(32, 8)>>>(W1, w1t, DIM, NF);
        k_tsplit<<<dim3(DIM / 32, NF / 32, NE), dim3(32, 8)>>>(W2, w2t, NF, DIM);
    }

    k_select_fused<<<dim3(NE, 32), 256>>>();
    k_eqfix<<<NE, 256>>>();

    k_gemm1_mma<<<dim3(NF / BN, NCAP / BM, NE), GTHREADS, DYN_SMEM>>>(b1);
    k_gemm2_mma<<<dim3(DIM / BN, NCAP / BM, NE), GTHREADS, DYN_SMEM>>>(b2);
    k_combine<<<N_TOK / 4, 512>>>(out);
}